// round 1
// baseline (speedup 1.0000x reference)
#include <cuda_runtime.h>
#include <math.h>

#define Bc  2
#define Ic  2048
#define Mc  2048
#define Dc  1024
#define Hc  16
#define Dhc 64
#define BHc 32   // Bc*Hc

// ---------------- scratch (static device globals; no allocs) ----------------
__device__ float  g_Q[BHc * (size_t)Ic * Dhc];   // [B,H,I,Dh]
__device__ float  g_K[BHc * (size_t)Mc * Dhc];   // [B,H,M,Dh]
__device__ float  g_V[BHc * (size_t)Mc * Dhc];   // [B,H,M,Dh]
__device__ float  g_O[Bc * (size_t)Ic * Dc];     // [B,I,D] (pre-Wo)
__device__ float2 g_stats[BHc * Ic];             // (rowmax, 1/rowsum)

// ---------------- 128x128x8 SIMT SGEMM core (fp32, 8x8 microtile) -----------
// C[4096 x 1024] = A[4096 x 1024] @ W[1024 x 1024]
__device__ __forceinline__ void gemm128(
    const float* __restrict__ A, const float* __restrict__ W,
    float* __restrict__ Cout, float scale, bool headmajor)
{
    __shared__ float As[8][128];
    __shared__ float Ws[8][128];

    const int tid  = threadIdx.x;
    const int row0 = blockIdx.y * 128;
    const int col0 = blockIdx.x * 128;
    const int tx   = tid & 15;       // 16 col-groups of 8
    const int ty   = tid >> 4;       // 16 row-groups of 8
    const int arow = tid >> 1;       // 0..127
    const int akq  = (tid & 1) * 4;  // 0 or 4
    const int wrow = tid >> 5;       // 0..7
    const int wcol = (tid & 31) * 4; // 0..124

    const float* Ap = A + (size_t)(row0 + arow) * Dc + akq;
    const float* Wp = W + (size_t)wrow * Dc + col0 + wcol;

    float acc[8][8];
#pragma unroll
    for (int i = 0; i < 8; i++)
#pragma unroll
        for (int j = 0; j < 8; j++) acc[i][j] = 0.0f;

    for (int k0 = 0; k0 < Dc; k0 += 8) {
        float4 a4 = *(const float4*)(Ap + k0);
        float4 w4 = *(const float4*)(Wp + (size_t)k0 * Dc);
        As[akq + 0][arow] = a4.x;
        As[akq + 1][arow] = a4.y;
        As[akq + 2][arow] = a4.z;
        As[akq + 3][arow] = a4.w;
        *(float4*)&Ws[wrow][wcol] = w4;
        __syncthreads();
#pragma unroll
        for (int kk = 0; kk < 8; kk++) {
            float a[8], b[8];
            *(float4*)&a[0] = *(const float4*)&As[kk][ty * 8];
            *(float4*)&a[4] = *(const float4*)&As[kk][ty * 8 + 4];
            *(float4*)&b[0] = *(const float4*)&Ws[kk][tx * 8];
            *(float4*)&b[4] = *(const float4*)&Ws[kk][tx * 8 + 4];
#pragma unroll
            for (int i = 0; i < 8; i++)
#pragma unroll
                for (int j = 0; j < 8; j++) acc[i][j] += a[i] * b[j];
        }
        __syncthreads();
    }

    // epilogue
#pragma unroll
    for (int ii = 0; ii < 8; ii++) {
        const int r  = row0 + ty * 8 + ii;
        const int b_ = r >> 11;          // r / 2048
        const int i_ = r & 2047;         // r % 2048
#pragma unroll
        for (int jj = 0; jj < 8; jj += 4) {
            const int c = col0 + tx * 8 + jj;
            float4 v = make_float4(acc[ii][jj] * scale, acc[ii][jj + 1] * scale,
                                   acc[ii][jj + 2] * scale, acc[ii][jj + 3] * scale);
            if (headmajor) {
                const int h = c >> 6, d = c & 63;
                *(float4*)&Cout[(((size_t)(b_ * Hc + h) * Ic + i_) * Dhc) + d] = v;
            } else {
                *(float4*)&Cout[(size_t)r * Dc + c] = v;
            }
        }
    }
}

// Q/K/V projections in a single launch (grid.z selects which)
__global__ __launch_bounds__(256) void qkv_kernel(
    const float* __restrict__ input, const float* __restrict__ memory,
    const float* __restrict__ Wq, const float* __restrict__ Wk,
    const float* __restrict__ Wv)
{
    if (blockIdx.z == 0)       gemm128(input,  Wq, g_Q, 0.125f, true);  // Dh^-0.5 = 1/8
    else if (blockIdx.z == 1)  gemm128(memory, Wk, g_K, 1.0f,   true);
    else                       gemm128(memory, Wv, g_V, 1.0f,   true);
}

__global__ __launch_bounds__(256) void out_kernel(
    const float* __restrict__ Wo, float* __restrict__ out)
{
    gemm128(g_O, Wo, out, 1.0f, false);
}

// ---------------- logits: S = Q K^T + bias, raw write + online (m, l) -------
// Block: 64 I-rows, loops M in tiles of 128. 256 threads, 4x8 microtile.
__global__ __launch_bounds__(256) void logits_kernel(
    const float* __restrict__ bias, float* __restrict__ align)
{
    __shared__ float QsT[64][68];    // [k][i]
    __shared__ float KsT[64][132];   // [k][m]

    const int tid = threadIdx.x;
    const int bh  = blockIdx.y;
    const int b   = bh >> 4;
    const int i0  = blockIdx.x * 64;
    const int tx  = tid & 15;        // m col-group (8 wide) -> 128
    const int ty  = tid >> 4;        // i row-group (4 tall) -> 64

    // load Q tile once (64 x 64)
#pragma unroll
    for (int t = 0; t < 4; t++) {
        const int fi = tid + t * 256;           // 0..1023
        const int r  = fi >> 4;
        const int kq = (fi & 15) * 4;
        float4 q4 = *(const float4*)&g_Q[((size_t)(bh * Ic + i0 + r)) * Dhc + kq];
        QsT[kq + 0][r] = q4.x; QsT[kq + 1][r] = q4.y;
        QsT[kq + 2][r] = q4.z; QsT[kq + 3][r] = q4.w;
    }

    float m_run[4], l_run[4];
#pragma unroll
    for (int r = 0; r < 4; r++) { m_run[r] = -3.402823466e38f; l_run[r] = 0.0f; }

    for (int m0 = 0; m0 < Mc; m0 += 128) {
        __syncthreads();   // protect KsT (prev iter) / QsT (first iter)
#pragma unroll
        for (int t = 0; t < 8; t++) {
            const int fi = tid + t * 256;       // 0..2047
            const int mr = fi >> 4;             // 0..127
            const int kq = (fi & 15) * 4;
            float4 k4 = *(const float4*)&g_K[((size_t)(bh * Mc + m0 + mr)) * Dhc + kq];
            KsT[kq + 0][mr] = k4.x; KsT[kq + 1][mr] = k4.y;
            KsT[kq + 2][mr] = k4.z; KsT[kq + 3][mr] = k4.w;
        }
        __syncthreads();

        float s[4][8];
#pragma unroll
        for (int r = 0; r < 4; r++)
#pragma unroll
            for (int j = 0; j < 8; j++) s[r][j] = 0.0f;

#pragma unroll 8
        for (int kk = 0; kk < 64; kk++) {
            float a[4], bb[8];
            *(float4*)&a[0]  = *(const float4*)&QsT[kk][ty * 4];
            *(float4*)&bb[0] = *(const float4*)&KsT[kk][tx * 8];
            *(float4*)&bb[4] = *(const float4*)&KsT[kk][tx * 8 + 4];
#pragma unroll
            for (int r = 0; r < 4; r++)
#pragma unroll
                for (int j = 0; j < 8; j++) s[r][j] += a[r] * bb[j];
        }

#pragma unroll
        for (int r = 0; r < 4; r++) {
            const int irow = i0 + ty * 4 + r;
            const float* bp = bias + ((size_t)(b * Ic + irow)) * Mc + m0 + tx * 8;
            float4 b0 = *(const float4*)bp;
            float4 b1 = *(const float4*)(bp + 4);
            s[r][0] += b0.x; s[r][1] += b0.y; s[r][2] += b0.z; s[r][3] += b0.w;
            s[r][4] += b1.x; s[r][5] += b1.y; s[r][6] += b1.z; s[r][7] += b1.w;

            float* ap = align + ((size_t)(bh * Ic + irow)) * Mc + m0 + tx * 8;
            *(float4*)ap       = make_float4(s[r][0], s[r][1], s[r][2], s[r][3]);
            *(float4*)(ap + 4) = make_float4(s[r][4], s[r][5], s[r][6], s[r][7]);

            // row stats: reduce over the 16 tx lanes (same 16-lane half)
            float mx = s[r][0];
#pragma unroll
            for (int j = 1; j < 8; j++) mx = fmaxf(mx, s[r][j]);
#pragma unroll
            for (int o = 1; o < 16; o <<= 1)
                mx = fmaxf(mx, __shfl_xor_sync(0xffffffffu, mx, o));
            const float mnew = fmaxf(m_run[r], mx);
            float ps = 0.0f;
#pragma unroll
            for (int j = 0; j < 8; j++) ps += __expf(s[r][j] - mnew);
#pragma unroll
            for (int o = 1; o < 16; o <<= 1)
                ps += __shfl_xor_sync(0xffffffffu, ps, o);
            l_run[r] = l_run[r] * __expf(m_run[r] - mnew) + ps;
            m_run[r] = mnew;
        }
    }

    if (tx == 0) {
#pragma unroll
        for (int r = 0; r < 4; r++) {
            const int irow = i0 + ty * 4 + r;
            g_stats[bh * Ic + irow] = make_float2(m_run[r], 1.0f / l_run[r]);
        }
    }
}

// ---------------- PV: normalize align in-place, O = P @ V -------------------
// Block: 128 I-rows x 64 Dh cols, loops M in tiles of 64. 256 threads, 4x8.
__global__ __launch_bounds__(256) void pv_kernel(float* __restrict__ align)
{
    __shared__ float PsT[64][132];   // [m][i]
    __shared__ float Vs[64][68];     // [m][d]

    const int tid = threadIdx.x;
    const int bh  = blockIdx.y;
    const int b   = bh >> 4, h = bh & 15;
    const int i0  = blockIdx.x * 128;
    const int tx  = tid & 7;         // d group (8 wide) -> 64
    const int ty  = tid >> 3;        // i group (4 tall) -> 128

    // preload per-row stats for the rows this thread touches in the S loads
    float2 st[8];
#pragma unroll
    for (int t = 0; t < 8; t++) {
        const int ir = (tid + t * 256) >> 4;    // 0..127
        st[t] = g_stats[bh * Ic + i0 + ir];
    }

    float acc[4][8];
#pragma unroll
    for (int r = 0; r < 4; r++)
#pragma unroll
        for (int j = 0; j < 8; j++) acc[r][j] = 0.0f;

    for (int m0 = 0; m0 < Mc; m0 += 64) {
        __syncthreads();
        // load raw S, normalize -> p, write p back (final align), stage to smem
#pragma unroll
        for (int t = 0; t < 8; t++) {
            const int fi = tid + t * 256;       // 0..2047
            const int ir = fi >> 4;             // 0..127
            const int mg = (fi & 15) * 4;
            float* ap = align + ((size_t)(bh * Ic + i0 + ir)) * Mc + m0 + mg;
            float4 s4 = *(const float4*)ap;
            float4 p4;
            p4.x = __expf(s4.x - st[t].x) * st[t].y;
            p4.y = __expf(s4.y - st[t].x) * st[t].y;
            p4.z = __expf(s4.z - st[t].x) * st[t].y;
            p4.w = __expf(s4.w - st[t].x) * st[t].y;
            *(float4*)ap = p4;
            PsT[mg + 0][ir] = p4.x; PsT[mg + 1][ir] = p4.y;
            PsT[mg + 2][ir] = p4.z; PsT[mg + 3][ir] = p4.w;
        }
#pragma unroll
        for (int t = 0; t < 4; t++) {
            const int fi = tid + t * 256;       // 0..1023
            const int mr = fi >> 4;             // 0..63
            const int dq = (fi & 15) * 4;
            *(float4*)&Vs[mr][dq] =
                *(const float4*)&g_V[((size_t)(bh * Mc + m0 + mr)) * Dhc + dq];
        }
        __syncthreads();

#pragma unroll 8
        for (int kk = 0; kk < 64; kk++) {
            float a[4], bb[8];
            *(float4*)&a[0]  = *(const float4*)&PsT[kk][ty * 4];
            *(float4*)&bb[0] = *(const float4*)&Vs[kk][tx * 8];
            *(float4*)&bb[4] = *(const float4*)&Vs[kk][tx * 8 + 4];
#pragma unroll
            for (int r = 0; r < 4; r++)
#pragma unroll
                for (int j = 0; j < 8; j++) acc[r][j] += a[r] * bb[j];
        }
    }

#pragma unroll
    for (int r = 0; r < 4; r++) {
        const int irow = i0 + ty * 4 + r;
        float* op = g_O + ((size_t)(b * Ic + irow)) * Dc + h * Dhc + tx * 8;
        *(float4*)op       = make_float4(acc[r][0], acc[r][1], acc[r][2], acc[r][3]);
        *(float4*)(op + 4) = make_float4(acc[r][4], acc[r][5], acc[r][6], acc[r][7]);
    }
}

// ---------------- launch ----------------------------------------------------
extern "C" void kernel_launch(void* const* d_in, const int* in_sizes, int n_in,
                              void* d_out, int out_size)
{
    const float* input  = (const float*)d_in[0];
    const float* memory = (const float*)d_in[1];
    const float* bias   = (const float*)d_in[2];
    const float* Wq     = (const float*)d_in[3];
    const float* Wk     = (const float*)d_in[4];
    const float* Wv     = (const float*)d_in[5];
    const float* Wo     = (const float*)d_in[6];

    float* out   = (float*)d_out;                  // [B,I,D]
    float* align = out + (size_t)Bc * Ic * Dc;     // [B,H,I,M]

    dim3 gqkv(Dc / 128, (Bc * Ic) / 128, 3);       // (8, 32, 3)
    qkv_kernel<<<gqkv, 256>>>(input, memory, Wq, Wk, Wv);

    logits_kernel<<<dim3(Ic / 64, BHc), 256>>>(bias, align);

    pv_kernel<<<dim3(Ic / 128, BHc), 256>>>(align);

    out_kernel<<<dim3(Dc / 128, (Bc * Ic) / 128), 256>>>(Wo, out);
}

// round 3
// speedup vs baseline: 1.2600x; 1.2600x over previous
#include <cuda_runtime.h>
#include <cuda_bf16.h>
#include <math.h>
#include <stdint.h>

#define Bc  2
#define Ic  2048
#define Mc  2048
#define Dc  1024
#define Hc  16
#define Dhc 64
#define BHc 32   // Bc*Hc

// ---------------- scratch (static device globals; no allocs) ----------------
__device__ float  g_Q[BHc * (size_t)Ic * Dhc];   // [B,H,I,Dh]
__device__ float  g_K[BHc * (size_t)Mc * Dhc];   // [B,H,M,Dh]
__device__ float  g_V[BHc * (size_t)Mc * Dhc];   // [B,H,M,Dh]
__device__ float  g_O[Bc * (size_t)Ic * Dc];     // [B,I,D] (pre-Wo)
__device__ float2 g_stats[BHc * Ic];             // (rowmax, 1/rowsum)

// ======================= mma.sync helpers (sm_80+ path) =====================
__device__ __forceinline__ uint32_t smem_u32(const void* p) {
    return (uint32_t)__cvta_generic_to_shared(p);
}
__device__ __forceinline__ void ldsm4(uint32_t addr, uint32_t* r) {
    asm volatile("ldmatrix.sync.aligned.m8n8.x4.shared.b16 {%0,%1,%2,%3}, [%4];"
                 : "=r"(r[0]), "=r"(r[1]), "=r"(r[2]), "=r"(r[3]) : "r"(addr));
}
__device__ __forceinline__ void ldsm4t(uint32_t addr, uint32_t* r) {
    asm volatile("ldmatrix.sync.aligned.m8n8.x4.trans.shared.b16 {%0,%1,%2,%3}, [%4];"
                 : "=r"(r[0]), "=r"(r[1]), "=r"(r[2]), "=r"(r[3]) : "r"(addr));
}
__device__ __forceinline__ void mma16816(float* c, const uint32_t* a, const uint32_t* b) {
    asm volatile(
        "mma.sync.aligned.m16n8k16.row.col.f32.bf16.bf16.f32 "
        "{%0,%1,%2,%3}, {%4,%5,%6,%7}, {%8,%9}, {%0,%1,%2,%3};"
        : "+f"(c[0]), "+f"(c[1]), "+f"(c[2]), "+f"(c[3])
        : "r"(a[0]), "r"(a[1]), "r"(a[2]), "r"(a[3]), "r"(b[0]), "r"(b[1]));
}
__device__ __forceinline__ void cvt_split(float x, float y,
                                          __nv_bfloat162& h, __nv_bfloat162& l) {
    __nv_bfloat16 hx = __float2bfloat16(x);
    __nv_bfloat16 hy = __float2bfloat16(y);
    h.x = hx; h.y = hy;
    l.x = __float2bfloat16(x - __bfloat162float(hx));
    l.y = __float2bfloat16(y - __bfloat162float(hy));
}

// ============ bf16-split tensor-core GEMM: C[4096x1024] = A @ W =============
// CTA tile 128x128, BK=32, double-buffered. 256 threads = 8 warps (64x32 each).
#define BKg     32
#define NCHUNK  (Dc / BKg)          // 32
#define A_PITCH 80                  // (32+8) bf16 -> bytes
#define B_PITCH 272                 // (128+8) bf16 -> bytes
#define A_BUF   (128 * A_PITCH)     // 10240 B
#define B_BUF   (BKg * B_PITCH)     // 8704 B
#define OFF_AH  0
#define OFF_AL  (2 * A_BUF)         // 20480
#define OFF_BH  (4 * A_BUF)         // 40960
#define OFF_BL  (OFF_BH + 2 * B_BUF)// 58368
#define SMEM_GEMM (OFF_BL + 2 * B_BUF) // 75776

__device__ __forceinline__ void gemm_sm(const float* __restrict__ A,
                                        const float* __restrict__ W,
                                        float* __restrict__ Cout,
                                        float scale, bool headmajor) {
    extern __shared__ char sm[];
    const uint32_t smb = smem_u32(sm);

    const int tid  = threadIdx.x;
    const int wid  = tid >> 5;
    const int lane = tid & 31;
    const int wr   = wid & 1;        // row half (64 rows)
    const int wc   = wid >> 1;       // col quarter (32 cols)
    const int row0 = blockIdx.y * 128;
    const int col0 = blockIdx.x * 128;

    // staging thread geometry (4 float4 each for A and W per chunk)
    int arow[4], ac4[4], wrow[4], wc4[4];
#pragma unroll
    for (int t = 0; t < 4; t++) {
        const int fi = tid + t * 256;        // 0..1023
        arow[t] = fi >> 3;  ac4[t] = (fi & 7) * 4;
        wrow[t] = fi >> 5;  wc4[t] = (fi & 31) * 4;
    }

    float4 ra[4], rw[4];
    auto ld_chunk = [&](int k0) {
#pragma unroll
        for (int t = 0; t < 4; t++) {
            ra[t] = *(const float4*)(A + (size_t)(row0 + arow[t]) * Dc + k0 + ac4[t]);
            rw[t] = *(const float4*)(W + (size_t)(k0 + wrow[t]) * Dc + col0 + wc4[t]);
        }
    };
    auto st_chunk = [&](int buf) {
#pragma unroll
        for (int t = 0; t < 4; t++) {
            __nv_bfloat162 h0, l0, h1, l1;
            cvt_split(ra[t].x, ra[t].y, h0, l0);
            cvt_split(ra[t].z, ra[t].w, h1, l1);
            const int ao = buf * A_BUF + arow[t] * A_PITCH + ac4[t] * 2;
            *(__nv_bfloat162*)(sm + OFF_AH + ao)     = h0;
            *(__nv_bfloat162*)(sm + OFF_AH + ao + 4) = h1;
            *(__nv_bfloat162*)(sm + OFF_AL + ao)     = l0;
            *(__nv_bfloat162*)(sm + OFF_AL + ao + 4) = l1;
            cvt_split(rw[t].x, rw[t].y, h0, l0);
            cvt_split(rw[t].z, rw[t].w, h1, l1);
            const int bo = buf * B_BUF + wrow[t] * B_PITCH + wc4[t] * 2;
            *(__nv_bfloat162*)(sm + OFF_BH + bo)     = h0;
            *(__nv_bfloat162*)(sm + OFF_BH + bo + 4) = h1;
            *(__nv_bfloat162*)(sm + OFF_BL + bo)     = l0;
            *(__nv_bfloat162*)(sm + OFF_BL + bo + 4) = l1;
        }
    };

    float Cf[4][4][4];
#pragma unroll
    for (int mi = 0; mi < 4; mi++)
#pragma unroll
        for (int nf = 0; nf < 4; nf++)
#pragma unroll
            for (int j = 0; j < 4; j++) Cf[mi][nf][j] = 0.0f;

    // prologue
    ld_chunk(0);
    st_chunk(0);
    __syncthreads();

    // fragment address components (constant across chunks)
    const uint32_t a_r  = (uint32_t)(wr * 64 + (lane & 7) + ((lane >> 3) & 1) * 8);
    const uint32_t a_cb = (uint32_t)((lane >> 4) * 16);
    const uint32_t b_r  = (uint32_t)(((lane >> 3) & 1) * 8 + (lane & 7));
    const uint32_t b_cb = (uint32_t)((wc * 32 + ((lane >> 4) & 1) * 8) * 2);

    for (int c = 0; c < NCHUNK; c++) {
        if (c + 1 < NCHUNK) ld_chunk((c + 1) * BKg);
        const int buf = c & 1;
        const uint32_t abase = smb + buf * A_BUF;
        const uint32_t bbase = smb + buf * B_BUF;

#pragma unroll
        for (int ks = 0; ks < BKg; ks += 16) {
            uint32_t ah[4][4], al[4][4], bh[4][2], bl[4][2];
#pragma unroll
            for (int mi = 0; mi < 4; mi++) {
                const uint32_t ao = (a_r + mi * 16) * A_PITCH + ks * 2 + a_cb;
                ldsm4(abase + OFF_AH + ao, ah[mi]);
                ldsm4(abase + OFF_AL + ao, al[mi]);
            }
#pragma unroll
            for (int half = 0; half < 2; half++) {
                const uint32_t bo = (ks + b_r) * B_PITCH + b_cb + half * 32;
                uint32_t t4[4];
                ldsm4t(bbase + OFF_BH + bo, t4);
                bh[half * 2][0] = t4[0]; bh[half * 2][1] = t4[1];
                bh[half * 2 + 1][0] = t4[2]; bh[half * 2 + 1][1] = t4[3];
                ldsm4t(bbase + OFF_BL + bo, t4);
                bl[half * 2][0] = t4[0]; bl[half * 2][1] = t4[1];
                bl[half * 2 + 1][0] = t4[2]; bl[half * 2 + 1][1] = t4[3];
            }
#pragma unroll
            for (int mi = 0; mi < 4; mi++)
#pragma unroll
                for (int nf = 0; nf < 4; nf++) {
                    mma16816(Cf[mi][nf], ah[mi], bh[nf]);
                    mma16816(Cf[mi][nf], al[mi], bh[nf]);
                    mma16816(Cf[mi][nf], ah[mi], bl[nf]);
                }
        }
        if (c + 1 < NCHUNK) st_chunk(1 - buf);
        __syncthreads();
    }

    // epilogue
#pragma unroll
    for (int mi = 0; mi < 4; mi++) {
        const int rg = row0 + wr * 64 + mi * 16 + (lane >> 2);
#pragma unroll
        for (int nf = 0; nf < 4; nf++) {
            const int cg = col0 + wc * 32 + nf * 8 + (lane & 3) * 2;
            float2 v0 = make_float2(Cf[mi][nf][0] * scale, Cf[mi][nf][1] * scale);
            float2 v1 = make_float2(Cf[mi][nf][2] * scale, Cf[mi][nf][3] * scale);
            if (headmajor) {
                const int h = cg >> 6, d = cg & 63;
                const int b0_ = rg >> 11, i0_ = rg & 2047;
                const int b1_ = (rg + 8) >> 11, i1_ = (rg + 8) & 2047;
                *(float2*)&Cout[(((size_t)(b0_ * Hc + h) * Ic + i0_) << 6) + d] = v0;
                *(float2*)&Cout[(((size_t)(b1_ * Hc + h) * Ic + i1_) << 6) + d] = v1;
            } else {
                *(float2*)&Cout[(size_t)rg * Dc + cg]       = v0;
                *(float2*)&Cout[(size_t)(rg + 8) * Dc + cg] = v1;
            }
        }
    }
}

// Q/K/V projections in a single launch (grid.z selects which)
__global__ __launch_bounds__(256) void qkv_kernel(
    const float* __restrict__ input, const float* __restrict__ memory,
    const float* __restrict__ Wq, const float* __restrict__ Wk,
    const float* __restrict__ Wv)
{
    if (blockIdx.z == 0)       gemm_sm(input,  Wq, g_Q, 0.125f, true);
    else if (blockIdx.z == 1)  gemm_sm(memory, Wk, g_K, 1.0f,   true);
    else                       gemm_sm(memory, Wv, g_V, 1.0f,   true);
}

__global__ __launch_bounds__(256) void out_kernel(
    const float* __restrict__ Wo, float* __restrict__ out)
{
    gemm_sm(g_O, Wo, out, 1.0f, false);
}

// ---------------- logits: S = Q K^T + bias, raw write + online (m, l) -------
__global__ __launch_bounds__(256) void logits_kernel(
    const float* __restrict__ bias, float* __restrict__ align)
{
    __shared__ float QsT[64][68];    // [k][i]
    __shared__ float KsT[64][132];   // [k][m]

    const int tid = threadIdx.x;
    const int bh  = blockIdx.y;
    const int b   = bh >> 4;
    const int i0  = blockIdx.x * 64;
    const int tx  = tid & 15;
    const int ty  = tid >> 4;

#pragma unroll
    for (int t = 0; t < 4; t++) {
        const int fi = tid + t * 256;
        const int r  = fi >> 4;
        const int kq = (fi & 15) * 4;
        float4 q4 = *(const float4*)&g_Q[((size_t)(bh * Ic + i0 + r)) * Dhc + kq];
        QsT[kq + 0][r] = q4.x; QsT[kq + 1][r] = q4.y;
        QsT[kq + 2][r] = q4.z; QsT[kq + 3][r] = q4.w;
    }

    float m_run[4], l_run[4];
#pragma unroll
    for (int r = 0; r < 4; r++) { m_run[r] = -3.402823466e38f; l_run[r] = 0.0f; }

    for (int m0 = 0; m0 < Mc; m0 += 128) {
        __syncthreads();
#pragma unroll
        for (int t = 0; t < 8; t++) {
            const int fi = tid + t * 256;
            const int mr = fi >> 4;
            const int kq = (fi & 15) * 4;
            float4 k4 = *(const float4*)&g_K[((size_t)(bh * Mc + m0 + mr)) * Dhc + kq];
            KsT[kq + 0][mr] = k4.x; KsT[kq + 1][mr] = k4.y;
            KsT[kq + 2][mr] = k4.z; KsT[kq + 3][mr] = k4.w;
        }
        __syncthreads();

        float s[4][8];
#pragma unroll
        for (int r = 0; r < 4; r++)
#pragma unroll
            for (int j = 0; j < 8; j++) s[r][j] = 0.0f;

#pragma unroll 8
        for (int kk = 0; kk < 64; kk++) {
            float a[4], bb[8];
            *(float4*)&a[0]  = *(const float4*)&QsT[kk][ty * 4];
            *(float4*)&bb[0] = *(const float4*)&KsT[kk][tx * 8];
            *(float4*)&bb[4] = *(const float4*)&KsT[kk][tx * 8 + 4];
#pragma unroll
            for (int r = 0; r < 4; r++)
#pragma unroll
                for (int j = 0; j < 8; j++) s[r][j] += a[r] * bb[j];
        }

#pragma unroll
        for (int r = 0; r < 4; r++) {
            const int irow = i0 + ty * 4 + r;
            const float* bp = bias + ((size_t)(b * Ic + irow)) * Mc + m0 + tx * 8;
            float4 b0 = *(const float4*)bp;
            float4 b1 = *(const float4*)(bp + 4);
            s[r][0] += b0.x; s[r][1] += b0.y; s[r][2] += b0.z; s[r][3] += b0.w;
            s[r][4] += b1.x; s[r][5] += b1.y; s[r][6] += b1.z; s[r][7] += b1.w;

            float* ap = align + ((size_t)(bh * Ic + irow)) * Mc + m0 + tx * 8;
            *(float4*)ap       = make_float4(s[r][0], s[r][1], s[r][2], s[r][3]);
            *(float4*)(ap + 4) = make_float4(s[r][4], s[r][5], s[r][6], s[r][7]);

            float mx = s[r][0];
#pragma unroll
            for (int j = 1; j < 8; j++) mx = fmaxf(mx, s[r][j]);
#pragma unroll
            for (int o = 1; o < 16; o <<= 1)
                mx = fmaxf(mx, __shfl_xor_sync(0xffffffffu, mx, o));
            const float mnew = fmaxf(m_run[r], mx);
            float ps = 0.0f;
#pragma unroll
            for (int j = 0; j < 8; j++) ps += __expf(s[r][j] - mnew);
#pragma unroll
            for (int o = 1; o < 16; o <<= 1)
                ps += __shfl_xor_sync(0xffffffffu, ps, o);
            l_run[r] = l_run[r] * __expf(m_run[r] - mnew) + ps;
            m_run[r] = mnew;
        }
    }

    if (tx == 0) {
#pragma unroll
        for (int r = 0; r < 4; r++) {
            const int irow = i0 + ty * 4 + r;
            g_stats[bh * Ic + irow] = make_float2(m_run[r], 1.0f / l_run[r]);
        }
    }
}

// ---------------- PV: normalize align in-place, O = P @ V -------------------
__global__ __launch_bounds__(256) void pv_kernel(float* __restrict__ align)
{
    __shared__ float PsT[64][132];   // [m][i]
    __shared__ float Vs[64][68];     // [m][d]

    const int tid = threadIdx.x;
    const int bh  = blockIdx.y;
    const int b   = bh >> 4, h = bh & 15;
    const int i0  = blockIdx.x * 128;
    const int tx  = tid & 7;
    const int ty  = tid >> 3;

    float2 st[8];
#pragma unroll
    for (int t = 0; t < 8; t++) {
        const int ir = (tid + t * 256) >> 4;
        st[t] = g_stats[bh * Ic + i0 + ir];
    }

    float acc[4][8];
#pragma unroll
    for (int r = 0; r < 4; r++)
#pragma unroll
        for (int j = 0; j < 8; j++) acc[r][j] = 0.0f;

    for (int m0 = 0; m0 < Mc; m0 += 64) {
        __syncthreads();
#pragma unroll
        for (int t = 0; t < 8; t++) {
            const int fi = tid + t * 256;
            const int ir = fi >> 4;
            const int mg = (fi & 15) * 4;
            float* ap = align + ((size_t)(bh * Ic + i0 + ir)) * Mc + m0 + mg;
            float4 s4 = *(const float4*)ap;
            float4 p4;
            p4.x = __expf(s4.x - st[t].x) * st[t].y;
            p4.y = __expf(s4.y - st[t].x) * st[t].y;
            p4.z = __expf(s4.z - st[t].x) * st[t].y;
            p4.w = __expf(s4.w - st[t].x) * st[t].y;
            *(float4*)ap = p4;
            PsT[mg + 0][ir] = p4.x; PsT[mg + 1][ir] = p4.y;
            PsT[mg + 2][ir] = p4.z; PsT[mg + 3][ir] = p4.w;
        }
#pragma unroll
        for (int t = 0; t < 4; t++) {
            const int fi = tid + t * 256;
            const int mr = fi >> 4;
            const int dq = (fi & 15) * 4;
            *(float4*)&Vs[mr][dq] =
                *(const float4*)&g_V[((size_t)(bh * Mc + m0 + mr)) * Dhc + dq];
        }
        __syncthreads();

#pragma unroll 8
        for (int kk = 0; kk < 64; kk++) {
            float a[4], bb[8];
            *(float4*)&a[0]  = *(const float4*)&PsT[kk][ty * 4];
            *(float4*)&bb[0] = *(const float4*)&Vs[kk][tx * 8];
            *(float4*)&bb[4] = *(const float4*)&Vs[kk][tx * 8 + 4];
#pragma unroll
            for (int r = 0; r < 4; r++)
#pragma unroll
                for (int j = 0; j < 8; j++) acc[r][j] += a[r] * bb[j];
        }
    }

#pragma unroll
    for (int r = 0; r < 4; r++) {
        const int irow = i0 + ty * 4 + r;
        float* op = g_O + ((size_t)(b * Ic + irow)) * Dc + h * Dhc + tx * 8;
        *(float4*)op       = make_float4(acc[r][0], acc[r][1], acc[r][2], acc[r][3]);
        *(float4*)(op + 4) = make_float4(acc[r][4], acc[r][5], acc[r][6], acc[r][7]);
    }
}

// ---------------- launch ----------------------------------------------------
extern "C" void kernel_launch(void* const* d_in, const int* in_sizes, int n_in,
                              void* d_out, int out_size)
{
    const float* input  = (const float*)d_in[0];
    const float* memory = (const float*)d_in[1];
    const float* bias   = (const float*)d_in[2];
    const float* Wq     = (const float*)d_in[3];
    const float* Wk     = (const float*)d_in[4];
    const float* Wv     = (const float*)d_in[5];
    const float* Wo     = (const float*)d_in[6];

    float* out   = (float*)d_out;                  // [B,I,D]
    float* align = out + (size_t)Bc * Ic * Dc;     // [B,H,I,M]

    static int attr_done = 0;
    if (!attr_done) {
        cudaFuncSetAttribute(qkv_kernel, cudaFuncAttributeMaxDynamicSharedMemorySize, SMEM_GEMM);
        cudaFuncSetAttribute(out_kernel, cudaFuncAttributeMaxDynamicSharedMemorySize, SMEM_GEMM);
        attr_done = 1;
    }

    dim3 gqkv(Dc / 128, (Bc * Ic) / 128, 3);       // (8, 32, 3)
    qkv_kernel<<<gqkv, 256, SMEM_GEMM>>>(input, memory, Wq, Wk, Wv);

    logits_kernel<<<dim3(Ic / 64, BHc), 256>>>(bias, align);

    pv_kernel<<<dim3(Ic / 128, BHc), 256>>>(align);

    out_kernel<<<dim3(Dc / 128, (Bc * Ic) / 128), 256, SMEM_GEMM>>>(Wo, out);
}

// round 4
// speedup vs baseline: 2.7700x; 2.1985x over previous
#include <cuda_runtime.h>
#include <cuda_bf16.h>
#include <math.h>
#include <stdint.h>

#define Bc  2
#define Ic  2048
#define Mc  2048
#define Dc  1024
#define Hc  16
#define Dhc 64
#define BHc 32   // Bc*Hc

// ---------------- scratch (static device globals; no allocs) ----------------
__device__ __nv_bfloat16 g_Qh[BHc * (size_t)Ic * Dhc];
__device__ __nv_bfloat16 g_Ql[BHc * (size_t)Ic * Dhc];
__device__ __nv_bfloat16 g_Kh[BHc * (size_t)Mc * Dhc];
__device__ __nv_bfloat16 g_Kl[BHc * (size_t)Mc * Dhc];
__device__ __nv_bfloat16 g_Vh[BHc * (size_t)Mc * Dhc];
__device__ __nv_bfloat16 g_Vl[BHc * (size_t)Mc * Dhc];
__device__ float  g_O[Bc * (size_t)Ic * Dc];     // [B,I,D] (pre-Wo)
__device__ float2 g_stats[BHc * Ic];             // (rowmax, 1/rowsum)

// ======================= mma.sync helpers (sm_80+ path) =====================
__device__ __forceinline__ uint32_t smem_u32(const void* p) {
    return (uint32_t)__cvta_generic_to_shared(p);
}
__device__ __forceinline__ void ldsm4(uint32_t addr, uint32_t* r) {
    asm volatile("ldmatrix.sync.aligned.m8n8.x4.shared.b16 {%0,%1,%2,%3}, [%4];"
                 : "=r"(r[0]), "=r"(r[1]), "=r"(r[2]), "=r"(r[3]) : "r"(addr));
}
__device__ __forceinline__ void ldsm4t(uint32_t addr, uint32_t* r) {
    asm volatile("ldmatrix.sync.aligned.m8n8.x4.trans.shared.b16 {%0,%1,%2,%3}, [%4];"
                 : "=r"(r[0]), "=r"(r[1]), "=r"(r[2]), "=r"(r[3]) : "r"(addr));
}
__device__ __forceinline__ void mma16816(float* c, const uint32_t* a, const uint32_t* b) {
    asm volatile(
        "mma.sync.aligned.m16n8k16.row.col.f32.bf16.bf16.f32 "
        "{%0,%1,%2,%3}, {%4,%5,%6,%7}, {%8,%9}, {%0,%1,%2,%3};"
        : "+f"(c[0]), "+f"(c[1]), "+f"(c[2]), "+f"(c[3])
        : "r"(a[0]), "r"(a[1]), "r"(a[2]), "r"(a[3]), "r"(b[0]), "r"(b[1]));
}
__device__ __forceinline__ void cvt_split(float x, float y,
                                          __nv_bfloat162& h, __nv_bfloat162& l) {
    __nv_bfloat16 hx = __float2bfloat16(x);
    __nv_bfloat16 hy = __float2bfloat16(y);
    h.x = hx; h.y = hy;
    l.x = __float2bfloat16(x - __bfloat162float(hx));
    l.y = __float2bfloat16(y - __bfloat162float(hy));
}
// fast exp on the FMA pipe (no MUFU): |rel err| ~1.5e-7, valid for x <= ~80
__device__ __forceinline__ float fexp(float x) {
    float y = fmaxf(x * 1.4426950408889634f, -126.0f);
    float z = y + 12582912.0f;               // round-to-nearest int (magic)
    int   n = __float_as_int(z) - 0x4B400000;
    float r = y - (z - 12582912.0f);         // [-0.5, 0.5]
    float w = r * 0.69314718055994531f;
    float p = fmaf(w, 1.3888889e-3f, 8.3333333e-3f);
    p = fmaf(w, p, 4.1666667e-2f);
    p = fmaf(w, p, 1.6666667e-1f);
    p = fmaf(w, p, 0.5f);
    p = fmaf(w, p, 1.0f);
    p = fmaf(w, p, 1.0f);
    return p * __int_as_float((n + 127) << 23);
}

// ============ bf16-split tensor-core GEMM: C[4096x1024] = A @ W =============
#define BKg     32
#define NCHUNK  (Dc / BKg)          // 32
#define A_PITCH 80
#define B_PITCH 272
#define A_BUF   (128 * A_PITCH)
#define B_BUF   (BKg * B_PITCH)
#define OFF_AH  0
#define OFF_AL  (2 * A_BUF)
#define OFF_BH  (4 * A_BUF)
#define OFF_BL  (OFF_BH + 2 * B_BUF)
#define SMEM_GEMM (OFF_BL + 2 * B_BUF) // 75776

__device__ __forceinline__ void gemm_sm(const float* __restrict__ A,
                                        const float* __restrict__ W,
                                        float* __restrict__ Cout,
                                        __nv_bfloat16* __restrict__ Ch,
                                        __nv_bfloat16* __restrict__ Cl,
                                        float scale, bool splitout) {
    extern __shared__ char sm[];
    const uint32_t smb = smem_u32(sm);

    const int tid  = threadIdx.x;
    const int wid  = tid >> 5;
    const int lane = tid & 31;
    const int wr   = wid & 1;
    const int wc   = wid >> 1;
    const int row0 = blockIdx.y * 128;
    const int col0 = blockIdx.x * 128;

    int arow[4], ac4[4], wrow[4], wc4[4];
#pragma unroll
    for (int t = 0; t < 4; t++) {
        const int fi = tid + t * 256;
        arow[t] = fi >> 3;  ac4[t] = (fi & 7) * 4;
        wrow[t] = fi >> 5;  wc4[t] = (fi & 31) * 4;
    }

    float4 ra[4], rw[4];
    auto ld_chunk = [&](int k0) {
#pragma unroll
        for (int t = 0; t < 4; t++) {
            ra[t] = *(const float4*)(A + (size_t)(row0 + arow[t]) * Dc + k0 + ac4[t]);
            rw[t] = *(const float4*)(W + (size_t)(k0 + wrow[t]) * Dc + col0 + wc4[t]);
        }
    };
    auto st_chunk = [&](int buf) {
#pragma unroll
        for (int t = 0; t < 4; t++) {
            __nv_bfloat162 h0, l0, h1, l1;
            cvt_split(ra[t].x, ra[t].y, h0, l0);
            cvt_split(ra[t].z, ra[t].w, h1, l1);
            const int ao = buf * A_BUF + arow[t] * A_PITCH + ac4[t] * 2;
            *(__nv_bfloat162*)(sm + OFF_AH + ao)     = h0;
            *(__nv_bfloat162*)(sm + OFF_AH + ao + 4) = h1;
            *(__nv_bfloat162*)(sm + OFF_AL + ao)     = l0;
            *(__nv_bfloat162*)(sm + OFF_AL + ao + 4) = l1;
            cvt_split(rw[t].x, rw[t].y, h0, l0);
            cvt_split(rw[t].z, rw[t].w, h1, l1);
            const int bo = buf * B_BUF + wrow[t] * B_PITCH + wc4[t] * 2;
            *(__nv_bfloat162*)(sm + OFF_BH + bo)     = h0;
            *(__nv_bfloat162*)(sm + OFF_BH + bo + 4) = h1;
            *(__nv_bfloat162*)(sm + OFF_BL + bo)     = l0;
            *(__nv_bfloat162*)(sm + OFF_BL + bo + 4) = l1;
        }
    };

    float Cf[4][4][4];
#pragma unroll
    for (int mi = 0; mi < 4; mi++)
#pragma unroll
        for (int nf = 0; nf < 4; nf++)
#pragma unroll
            for (int j = 0; j < 4; j++) Cf[mi][nf][j] = 0.0f;

    ld_chunk(0);
    st_chunk(0);
    __syncthreads();

    const uint32_t a_r  = (uint32_t)(wr * 64 + (lane & 7) + ((lane >> 3) & 1) * 8);
    const uint32_t a_cb = (uint32_t)((lane >> 4) * 16);
    const uint32_t b_r  = (uint32_t)(((lane >> 3) & 1) * 8 + (lane & 7));
    const uint32_t b_cb = (uint32_t)((wc * 32 + ((lane >> 4) & 1) * 8) * 2);

    for (int c = 0; c < NCHUNK; c++) {
        if (c + 1 < NCHUNK) ld_chunk((c + 1) * BKg);
        const int buf = c & 1;
        const uint32_t abase = smb + buf * A_BUF;
        const uint32_t bbase = smb + buf * B_BUF;

#pragma unroll
        for (int ks = 0; ks < BKg; ks += 16) {
            uint32_t ah[4][4], al[4][4], bh[4][2], bl[4][2];
#pragma unroll
            for (int mi = 0; mi < 4; mi++) {
                const uint32_t ao = (a_r + mi * 16) * A_PITCH + ks * 2 + a_cb;
                ldsm4(abase + OFF_AH + ao, ah[mi]);
                ldsm4(abase + OFF_AL + ao, al[mi]);
            }
#pragma unroll
            for (int half = 0; half < 2; half++) {
                const uint32_t bo = (ks + b_r) * B_PITCH + b_cb + half * 32;
                uint32_t t4[4];
                ldsm4t(bbase + OFF_BH + bo, t4);
                bh[half * 2][0] = t4[0]; bh[half * 2][1] = t4[1];
                bh[half * 2 + 1][0] = t4[2]; bh[half * 2 + 1][1] = t4[3];
                ldsm4t(bbase + OFF_BL + bo, t4);
                bl[half * 2][0] = t4[0]; bl[half * 2][1] = t4[1];
                bl[half * 2 + 1][0] = t4[2]; bl[half * 2 + 1][1] = t4[3];
            }
#pragma unroll
            for (int mi = 0; mi < 4; mi++)
#pragma unroll
                for (int nf = 0; nf < 4; nf++) {
                    mma16816(Cf[mi][nf], ah[mi], bh[nf]);
                    mma16816(Cf[mi][nf], al[mi], bh[nf]);
                    mma16816(Cf[mi][nf], ah[mi], bl[nf]);
                }
        }
        if (c + 1 < NCHUNK) st_chunk(1 - buf);
        __syncthreads();
    }

#pragma unroll
    for (int mi = 0; mi < 4; mi++) {
        const int rg = row0 + wr * 64 + mi * 16 + (lane >> 2);
#pragma unroll
        for (int nf = 0; nf < 4; nf++) {
            const int cg = col0 + wc * 32 + nf * 8 + (lane & 3) * 2;
            float2 v0 = make_float2(Cf[mi][nf][0] * scale, Cf[mi][nf][1] * scale);
            float2 v1 = make_float2(Cf[mi][nf][2] * scale, Cf[mi][nf][3] * scale);
            if (splitout) {
                const int h = cg >> 6, d = cg & 63;
                const int b0_ = rg >> 11, i0_ = rg & 2047;
                const int b1_ = (rg + 8) >> 11, i1_ = (rg + 8) & 2047;
                const size_t idx0 = (((size_t)(b0_ * Hc + h) * Ic + i0_) << 6) + d;
                const size_t idx1 = (((size_t)(b1_ * Hc + h) * Ic + i1_) << 6) + d;
                __nv_bfloat162 hh, ll;
                cvt_split(v0.x, v0.y, hh, ll);
                *(__nv_bfloat162*)(Ch + idx0) = hh;
                *(__nv_bfloat162*)(Cl + idx0) = ll;
                cvt_split(v1.x, v1.y, hh, ll);
                *(__nv_bfloat162*)(Ch + idx1) = hh;
                *(__nv_bfloat162*)(Cl + idx1) = ll;
            } else {
                *(float2*)&Cout[(size_t)rg * Dc + cg]       = v0;
                *(float2*)&Cout[(size_t)(rg + 8) * Dc + cg] = v1;
            }
        }
    }
}

__global__ __launch_bounds__(256) void qkv_kernel(
    const float* __restrict__ input, const float* __restrict__ memory,
    const float* __restrict__ Wq, const float* __restrict__ Wk,
    const float* __restrict__ Wv)
{
    if (blockIdx.z == 0)       gemm_sm(input,  Wq, nullptr, g_Qh, g_Ql, 0.125f, true);
    else if (blockIdx.z == 1)  gemm_sm(memory, Wk, nullptr, g_Kh, g_Kl, 1.0f,   true);
    else                       gemm_sm(memory, Wv, nullptr, g_Vh, g_Vl, 1.0f,   true);
}

__global__ __launch_bounds__(256) void out_kernel(
    const float* __restrict__ Wo, float* __restrict__ out)
{
    gemm_sm(g_O, Wo, out, nullptr, nullptr, 1.0f, false);
}

// =================== logits: S = Q K^T + bias (tensorized) ==================
// Block: (bh, i0*128). 8 warps, each owns 16 I-rows x 64 M-cols per step.
// M loop: 32 steps of 64. Q frags in registers; K double-buffered in smem.
#define LP 144              // row pitch bytes (64 bf16 + 16B pad)
#define LKBUF 9216          // 64 rows * 144
__global__ __launch_bounds__(256) void logits_kernel(
    const float* __restrict__ bias, float* __restrict__ align)
{
    __shared__ char sm[4 * LKBUF];   // 36864: Q staging overlays K double buffers
    const uint32_t smb = smem_u32(sm);
    const int tid = threadIdx.x, wid = tid >> 5, lane = tid & 31;
    const int bh = blockIdx.y, b = bh >> 4;
    const int i0 = blockIdx.x * 128;

    // ---- stage Q (h at 0, l at 18432), 128 rows x 128B ----
#pragma unroll
    for (int t = 0; t < 4; t++) {
        const int fi = tid + t * 256;            // 0..1023
        const int r = fi >> 3, c = fi & 7;
        const size_t gi = ((size_t)bh * Ic + i0 + r) * 64;
        *(uint4*)(sm + r * LP + c * 16)             = *((const uint4*)(g_Qh + gi) + c);
        *(uint4*)(sm + 2 * LKBUF + r * LP + c * 16) = *((const uint4*)(g_Ql + gi) + c);
    }
    __syncthreads();

    // ---- Q fragments to registers ----
    uint32_t qh[4][4], ql[4][4];
    const uint32_t a_off = (uint32_t)((wid * 16 + (lane & 7) + ((lane >> 3) & 1) * 8) * LP
                                      + (lane >> 4) * 16);
#pragma unroll
    for (int ks = 0; ks < 4; ks++) {
        ldsm4(smb + a_off + ks * 32, qh[ks]);
        ldsm4(smb + 2 * LKBUF + a_off + ks * 32, ql[ks]);
    }
    __syncthreads();

    // ---- stage K step 0 into buffer 0 ----
    auto stageK = [&](int m0, int base) {
#pragma unroll
        for (int t = 0; t < 2; t++) {
            const int fi = tid + t * 256;        // 0..511
            const int r = fi >> 3, c = fi & 7;
            const size_t gi = ((size_t)bh * Mc + m0 + r) * 64;
            *(uint4*)(sm + base + r * LP + c * 16)         = *((const uint4*)(g_Kh + gi) + c);
            *(uint4*)(sm + base + LKBUF + r * LP + c * 16) = *((const uint4*)(g_Kl + gi) + c);
        }
    };
    stageK(0, 0);
    __syncthreads();

    const int r0 = lane >> 2;        // row within warp's 16 (and +8)
    float m_run[2] = {-3.402823466e38f, -3.402823466e38f};
    float l_run[2] = {0.0f, 0.0f};

    const uint32_t b_row = (uint32_t)((lane & 7) + (lane >> 4) * 8);
    const uint32_t b_kb  = (uint32_t)(((lane >> 3) & 1) * 16);

    for (int c = 0; c < 32; c++) {
        const int m0 = c * 64;
        const int buf = (c & 1) * 2 * LKBUF;

        float Cf[8][4];
#pragma unroll
        for (int nf = 0; nf < 8; nf++)
#pragma unroll
            for (int j = 0; j < 4; j++) Cf[nf][j] = 0.0f;

#pragma unroll
        for (int ks = 0; ks < 4; ks++) {
            uint32_t kh[8][2], kl[8][2];
#pragma unroll
            for (int mg = 0; mg < 4; mg++) {
                const uint32_t baddr = smb + buf + (mg * 16 + b_row) * LP + ks * 32 + b_kb;
                uint32_t t4[4];
                ldsm4(baddr, t4);
                kh[mg * 2][0] = t4[0]; kh[mg * 2][1] = t4[1];
                kh[mg * 2 + 1][0] = t4[2]; kh[mg * 2 + 1][1] = t4[3];
                ldsm4(baddr + LKBUF, t4);
                kl[mg * 2][0] = t4[0]; kl[mg * 2][1] = t4[1];
                kl[mg * 2 + 1][0] = t4[2]; kl[mg * 2 + 1][1] = t4[3];
            }
#pragma unroll
            for (int nf = 0; nf < 8; nf++) {
                mma16816(Cf[nf], qh[ks], kh[nf]);
                mma16816(Cf[nf], ql[ks], kh[nf]);
                mma16816(Cf[nf], qh[ks], kl[nf]);
            }
        }

        // ---- epilogue: bias add, align store, online stats ----
        float mx[2] = {-3.402823466e38f, -3.402823466e38f};
#pragma unroll
        for (int nf = 0; nf < 8; nf++) {
            const int col = m0 + nf * 8 + (lane & 3) * 2;
#pragma unroll
            for (int rr = 0; rr < 2; rr++) {
                const int irow = i0 + wid * 16 + r0 + rr * 8;
                const float2 bv = *(const float2*)(bias + ((size_t)(b * Ic) + irow) * Mc + col);
                float s0 = Cf[nf][rr * 2 + 0] + bv.x;
                float s1 = Cf[nf][rr * 2 + 1] + bv.y;
                Cf[nf][rr * 2 + 0] = s0; Cf[nf][rr * 2 + 1] = s1;
                *(float2*)(align + ((size_t)(bh * Ic) + irow) * Mc + col) = make_float2(s0, s1);
                mx[rr] = fmaxf(mx[rr], fmaxf(s0, s1));
            }
        }
#pragma unroll
        for (int rr = 0; rr < 2; rr++) {
            mx[rr] = fmaxf(mx[rr], __shfl_xor_sync(0xffffffffu, mx[rr], 1));
            mx[rr] = fmaxf(mx[rr], __shfl_xor_sync(0xffffffffu, mx[rr], 2));
            const float mnew = fmaxf(m_run[rr], mx[rr]);
            const float sc = fexp(m_run[rr] - mnew);
            float ps = 0.0f;
#pragma unroll
            for (int nf = 0; nf < 8; nf++)
                ps += fexp(Cf[nf][rr * 2] - mnew) + fexp(Cf[nf][rr * 2 + 1] - mnew);
            ps += __shfl_xor_sync(0xffffffffu, ps, 1);
            ps += __shfl_xor_sync(0xffffffffu, ps, 2);
            l_run[rr] = l_run[rr] * sc + ps;
            m_run[rr] = mnew;
        }

        if (c + 1 < 32) {
            __syncthreads();
            stageK((c + 1) * 64, (1 - (c & 1)) * 2 * LKBUF);
            __syncthreads();
        }
    }

    if ((lane & 3) == 0) {
#pragma unroll
        for (int rr = 0; rr < 2; rr++) {
            const int irow = i0 + wid * 16 + r0 + rr * 8;
            g_stats[bh * Ic + irow] = make_float2(m_run[rr], 1.0f / l_run[rr]);
        }
    }
}

// ============== PV: normalize align in-place, O = P @ V (tensorized) ========
// Block: (bh, i0*128). Warp tile 16 I-rows x 64 Dh. M loop: 32 steps of 64.
#define PV_PL   0            // Ph [128][144]
#define PV_PLL  18432        // Pl
#define PV_VH   36864        // Vh [64][144]
#define PV_VL   46080        // Vl
#define SMEM_PV 55296
__global__ __launch_bounds__(256) void pv_kernel(float* __restrict__ align)
{
    extern __shared__ char smp[];
    const uint32_t smb = smem_u32(smp);
    const int tid = threadIdx.x, wid = tid >> 5, lane = tid & 31;
    const int bh = blockIdx.y, b = bh >> 4, h = bh & 15;
    const int i0 = blockIdx.x * 128;

    int irA[8], mgA[8];
    float2 st[8];
#pragma unroll
    for (int t = 0; t < 8; t++) {
        const int fi = tid + t * 256;
        irA[t] = fi >> 4;
        mgA[t] = (fi & 15) * 4;
        st[t] = g_stats[bh * Ic + i0 + irA[t]];
    }

    float Cf[8][4];
#pragma unroll
    for (int nf = 0; nf < 8; nf++)
#pragma unroll
        for (int j = 0; j < 4; j++) Cf[nf][j] = 0.0f;

    float4 sreg[8];
    auto ldS = [&](int m0) {
#pragma unroll
        for (int t = 0; t < 8; t++)
            sreg[t] = *(const float4*)(align + ((size_t)(bh * Ic) + i0 + irA[t]) * Mc + m0 + mgA[t]);
    };
    ldS(0);

    const uint32_t a_off = (uint32_t)((wid * 16 + (lane & 7) + ((lane >> 3) & 1) * 8) * LP
                                      + (lane >> 4) * 16);
    const uint32_t vb_r = (uint32_t)(((lane >> 3) & 1) * 8 + (lane & 7));
    const uint32_t vb_c = (uint32_t)(((lane >> 4) & 1) * 16);   // 8 elems * 2B

    for (int c = 0; c < 32; c++) {
        const int m0 = c * 64;

        // stage P: exp + normalize, write final align, split to smem
#pragma unroll
        for (int t = 0; t < 8; t++) {
            float4 s4 = sreg[t];
            float4 p4;
            p4.x = fexp(s4.x - st[t].x) * st[t].y;
            p4.y = fexp(s4.y - st[t].x) * st[t].y;
            p4.z = fexp(s4.z - st[t].x) * st[t].y;
            p4.w = fexp(s4.w - st[t].x) * st[t].y;
            *(float4*)(align + ((size_t)(bh * Ic) + i0 + irA[t]) * Mc + m0 + mgA[t]) = p4;
            __nv_bfloat162 h0, l0, h1, l1;
            cvt_split(p4.x, p4.y, h0, l0);
            cvt_split(p4.z, p4.w, h1, l1);
            const int base = irA[t] * LP + mgA[t] * 2;
            *(__nv_bfloat162*)(smp + PV_PL + base)      = h0;
            *(__nv_bfloat162*)(smp + PV_PL + base + 4)  = h1;
            *(__nv_bfloat162*)(smp + PV_PLL + base)     = l0;
            *(__nv_bfloat162*)(smp + PV_PLL + base + 4) = l1;
        }
        // stage V
#pragma unroll
        for (int t = 0; t < 2; t++) {
            const int fi = tid + t * 256;
            const int r = fi >> 3, cc = fi & 7;
            const size_t gi = ((size_t)bh * Mc + m0 + r) * 64;
            *(uint4*)(smp + PV_VH + r * LP + cc * 16) = *((const uint4*)(g_Vh + gi) + cc);
            *(uint4*)(smp + PV_VL + r * LP + cc * 16) = *((const uint4*)(g_Vl + gi) + cc);
        }
        __syncthreads();

        if (c + 1 < 32) ldS((c + 1) * 64);   // prefetch next S (hidden under MMA)

#pragma unroll
        for (int ks = 0; ks < 4; ks++) {
            uint32_t ph[4], pl[4];
            ldsm4(smb + PV_PL + a_off + ks * 32, ph);
            ldsm4(smb + PV_PLL + a_off + ks * 32, pl);
            uint32_t vh[8][2], vl[8][2];
#pragma unroll
            for (int q = 0; q < 4; q++) {
                const uint32_t vaddr = smb + PV_VH + (ks * 16 + vb_r) * LP + q * 32 + vb_c;
                uint32_t t4[4];
                ldsm4t(vaddr, t4);
                vh[q * 2][0] = t4[0]; vh[q * 2][1] = t4[1];
                vh[q * 2 + 1][0] = t4[2]; vh[q * 2 + 1][1] = t4[3];
                ldsm4t(vaddr + (PV_VL - PV_VH), t4);
                vl[q * 2][0] = t4[0]; vl[q * 2][1] = t4[1];
                vl[q * 2 + 1][0] = t4[2]; vl[q * 2 + 1][1] = t4[3];
            }
#pragma unroll
            for (int nf = 0; nf < 8; nf++) {
                mma16816(Cf[nf], ph, vh[nf]);
                mma16816(Cf[nf], pl, vh[nf]);
                mma16816(Cf[nf], ph, vl[nf]);
            }
        }
        __syncthreads();
    }

    // epilogue: O -> g_O fp32 [b][i][h*64+d]
#pragma unroll
    for (int nf = 0; nf < 8; nf++) {
        const int d = nf * 8 + (lane & 3) * 2;
        const int rg = i0 + wid * 16 + (lane >> 2);
        *(float2*)(g_O + ((size_t)(b * Ic) + rg) * Dc + h * 64 + d) =
            make_float2(Cf[nf][0], Cf[nf][1]);
        *(float2*)(g_O + ((size_t)(b * Ic) + rg + 8) * Dc + h * 64 + d) =
            make_float2(Cf[nf][2], Cf[nf][3]);
    }
}

// ---------------- launch ----------------------------------------------------
extern "C" void kernel_launch(void* const* d_in, const int* in_sizes, int n_in,
                              void* d_out, int out_size)
{
    const float* input  = (const float*)d_in[0];
    const float* memory = (const float*)d_in[1];
    const float* bias   = (const float*)d_in[2];
    const float* Wq     = (const float*)d_in[3];
    const float* Wk     = (const float*)d_in[4];
    const float* Wv     = (const float*)d_in[5];
    const float* Wo     = (const float*)d_in[6];

    float* out   = (float*)d_out;                  // [B,I,D]
    float* align = out + (size_t)Bc * Ic * Dc;     // [B,H,I,M]

    static int attr_done = 0;
    if (!attr_done) {
        cudaFuncSetAttribute(qkv_kernel, cudaFuncAttributeMaxDynamicSharedMemorySize, SMEM_GEMM);
        cudaFuncSetAttribute(out_kernel, cudaFuncAttributeMaxDynamicSharedMemorySize, SMEM_GEMM);
        cudaFuncSetAttribute(pv_kernel,  cudaFuncAttributeMaxDynamicSharedMemorySize, SMEM_PV);
        attr_done = 1;
    }

    dim3 gqkv(Dc / 128, (Bc * Ic) / 128, 3);       // (8, 32, 3)
    qkv_kernel<<<gqkv, 256, SMEM_GEMM>>>(input, memory, Wq, Wk, Wv);

    logits_kernel<<<dim3(Ic / 128, BHc), 256>>>(bias, align);

    pv_kernel<<<dim3(Ic / 128, BHc), 256, SMEM_PV>>>(align);

    out_kernel<<<dim3(Dc / 128, (Bc * Ic) / 128), 256, SMEM_GEMM>>>(Wo, out);
}